// round 3
// baseline (speedup 1.0000x reference)
#include <cuda_runtime.h>
#include <cuda_fp16.h>
#include <math.h>
#include <stdint.h>

#define NN 100000
#define EE 1600000
#define DD 256
#define DE 8
#define HF 128
#define NEG_SLOPE 0.2f

// ---------------- scratch (device globals) ----------------------------------
__device__ __half  g_hsrc_h[(size_t)NN * HF];   // fp16 h_src (gather payload)
__device__ float   g_hdst[(size_t)NN * HF];
__device__ float   g_rst [(size_t)NN * HF];
__device__ float2  g_asrc[NN];
__device__ float2  g_adst[NN];
__device__ float2  g_ep  [EE];                  // exp(e) in CSR order
__device__ int     g_cnt [NN];
__device__ int     g_off [NN + 1];
__device__ int     g_cur [NN];
__device__ int     g_psrc[EE];                  // src node per CSR slot
__device__ int     g_epos[EE];                  // edge i -> CSR slot

// ---------------- f32x2 helpers (FFMA2) -------------------------------------
static __device__ __forceinline__ unsigned long long pack2(float lo, float hi) {
    unsigned long long r;
    asm("mov.b64 %0, {%1,%2};" : "=l"(r) : "f"(lo), "f"(hi));
    return r;
}
static __device__ __forceinline__ void fma2(unsigned long long& d,
                                            unsigned long long a,
                                            unsigned long long b) {
    asm("fma.rn.f32x2 %0, %1, %2, %0;" : "+l"(d) : "l"(a), "l"(b));
}
static __device__ __forceinline__ float2 unpack2(unsigned long long v) {
    float lo, hi;
    asm("mov.b64 {%0,%1}, %2;" : "=f"(lo), "=f"(hi) : "l"(v));
    return make_float2(lo, hi);
}

// ---------------- CSR build --------------------------------------------------
__global__ void hist_kernel(const int* __restrict__ ed) {
    int i = blockIdx.x * blockDim.x + threadIdx.x;
    if (i < EE) atomicAdd(&g_cnt[ed[i]], 1);
}

__global__ void scan_kernel() {
    __shared__ int ssum[1024];
    int t = threadIdx.x;
    const int CH = (NN + 1023) / 1024;
    int beg = t * CH;
    int end = min(beg + CH, NN);
    int s = 0;
    for (int i = beg; i < end; i++) s += g_cnt[i];
    ssum[t] = s;
    __syncthreads();
#pragma unroll
    for (int off = 1; off < 1024; off <<= 1) {
        int add = (t >= off) ? ssum[t - off] : 0;
        __syncthreads();
        ssum[t] += add;
        __syncthreads();
    }
    int base = (t == 0) ? 0 : ssum[t - 1];
    for (int i = beg; i < end; i++) {
        g_off[i] = base;
        g_cur[i] = base;
        base += g_cnt[i];
    }
    if (t == 1023) g_off[NN] = EE;
}

__global__ void scatter_kernel(const int* __restrict__ es,
                               const int* __restrict__ ed) {
    int i = blockIdx.x * blockDim.x + threadIdx.x;
    if (i >= EE) return;
    int pos = atomicAdd(&g_cur[ed[i]], 1);
    g_psrc[pos] = es[i];
    g_epos[i] = pos;
}

// ---------------- GEMM: C[*,128] = A[M,K] @ B[128,K]^T, FFMA2 ---------------
// blockIdx.x selects weights/out; Ch!=null && blockIdx.x==0 -> fp16 output
__global__ void __launch_bounds__(256, 2)
gemm_kernel(const float* __restrict__ A,
            const float* __restrict__ B0, const float* __restrict__ B1,
            const float* __restrict__ bias0, const float* __restrict__ bias1,
            const float* __restrict__ add,
            float* __restrict__ C0, float* __restrict__ C1,
            __half* __restrict__ Ch,
            int M, int K, int mode) {
    __shared__ float As[16][132];
    __shared__ float Bs[16][132];

    const float* B    = (blockIdx.x == 0) ? B0 : B1;
    const float* bias = (blockIdx.x == 0) ? bias0 : bias1;
    float*       C    = (blockIdx.x == 0) ? C0 : C1;
    bool half_out     = (blockIdx.x == 0) && (Ch != nullptr);

    int bm = blockIdx.y * 128;
    int t  = threadIdx.x;
    int tx = t & 15, ty = t >> 4;
    int lr = t >> 2;
    int lc = (t & 3) * 4;

    unsigned long long acc[8][4];
#pragma unroll
    for (int i = 0; i < 8; i++)
#pragma unroll
        for (int j = 0; j < 4; j++) acc[i][j] = pack2(0.f, 0.f);

    for (int kt = 0; kt < K; kt += 16) {
#pragma unroll
        for (int h = 0; h < 2; h++) {
            int r = lr + h * 64;
            int arow = bm + r;
            float4 av = make_float4(0.f, 0.f, 0.f, 0.f);
            if (arow < M) av = *(const float4*)(A + (size_t)arow * K + kt + lc);
            As[lc + 0][r] = av.x; As[lc + 1][r] = av.y;
            As[lc + 2][r] = av.z; As[lc + 3][r] = av.w;
            float4 bv = *(const float4*)(B + (size_t)r * K + kt + lc);
            Bs[lc + 0][r] = bv.x; Bs[lc + 1][r] = bv.y;
            Bs[lc + 2][r] = bv.z; Bs[lc + 3][r] = bv.w;
        }
        __syncthreads();

#pragma unroll
        for (int kk = 0; kk < 16; kk++) {
            float4 a0 = *(const float4*)&As[kk][ty * 8];
            float4 a1 = *(const float4*)&As[kk][ty * 8 + 4];
            ulonglong2 b01 = *(const ulonglong2*)&Bs[kk][tx * 8];
            ulonglong2 b23 = *(const ulonglong2*)&Bs[kk][tx * 8 + 4];
            float av[8] = {a0.x, a0.y, a0.z, a0.w, a1.x, a1.y, a1.z, a1.w};
#pragma unroll
            for (int i = 0; i < 8; i++) {
                unsigned long long ad = pack2(av[i], av[i]);
                fma2(acc[i][0], ad, b01.x);
                fma2(acc[i][1], ad, b01.y);
                fma2(acc[i][2], ad, b23.x);
                fma2(acc[i][3], ad, b23.y);
            }
        }
        __syncthreads();
    }

    int cbase = tx * 8;
    float b8[8];
#pragma unroll
    for (int j = 0; j < 8; j++) b8[j] = 0.f;
    if (bias) {
        float4 q0 = *(const float4*)(bias + cbase);
        float4 q1 = *(const float4*)(bias + cbase + 4);
        b8[0] = q0.x; b8[1] = q0.y; b8[2] = q0.z; b8[3] = q0.w;
        b8[4] = q1.x; b8[5] = q1.y; b8[6] = q1.z; b8[7] = q1.w;
    }
#pragma unroll
    for (int i = 0; i < 8; i++) {
        int row = bm + ty * 8 + i;
        if (row >= M) continue;
        float o[8];
#pragma unroll
        for (int j = 0; j < 4; j++) {
            float2 p = unpack2(acc[i][j]);
            o[2 * j]     = p.x + b8[2 * j];
            o[2 * j + 1] = p.y + b8[2 * j + 1];
        }
        if (mode == 1) {
            float4 r0 = *(const float4*)(add + (size_t)row * HF + cbase);
            float4 r1 = *(const float4*)(add + (size_t)row * HF + cbase + 4);
            o[0] = fmaxf(o[0], 0.f) + r0.x; o[1] = fmaxf(o[1], 0.f) + r0.y;
            o[2] = fmaxf(o[2], 0.f) + r0.z; o[3] = fmaxf(o[3], 0.f) + r0.w;
            o[4] = fmaxf(o[4], 0.f) + r1.x; o[5] = fmaxf(o[5], 0.f) + r1.y;
            o[6] = fmaxf(o[6], 0.f) + r1.z; o[7] = fmaxf(o[7], 0.f) + r1.w;
        }
        if (half_out) {
            __half2 hh[4];
#pragma unroll
            for (int j = 0; j < 4; j++)
                hh[j] = __floats2half2_rn(o[2 * j], o[2 * j + 1]);
            *(uint4*)(Ch + (size_t)row * HF + cbase) = *(uint4*)hh;
        } else {
            *(float4*)(C + (size_t)row * HF + cbase) =
                make_float4(o[0], o[1], o[2], o[3]);
            *(float4*)(C + (size_t)row * HF + cbase + 4) =
                make_float4(o[4], o[5], o[6], o[7]);
        }
    }
}

// ---------------- per-node attention logits ---------------------------------
static __device__ __forceinline__ float dot8(float4 x0, float4 x1,
                                             float4 w0, float4 w1) {
    float s = x0.x * w0.x;
    s = fmaf(x0.y, w0.y, s); s = fmaf(x0.z, w0.z, s); s = fmaf(x0.w, w0.w, s);
    s = fmaf(x1.x, w1.x, s); s = fmaf(x1.y, w1.y, s);
    s = fmaf(x1.z, w1.z, s); s = fmaf(x1.w, w1.w, s);
    return s;
}

__global__ void attn_kernel(const float* __restrict__ feat,
                            const float* __restrict__ Was,
                            const float* __restrict__ Wad) {
    int lane = threadIdx.x & 31;
    int warp = (blockIdx.x * blockDim.x + threadIdx.x) >> 5;
    int nwarps = (gridDim.x * blockDim.x) >> 5;
    int cb = lane * 8;

    float4 ws0a = *(const float4*)(Was + cb);
    float4 ws0b = *(const float4*)(Was + cb + 4);
    float4 ws1a = *(const float4*)(Was + DD + cb);
    float4 ws1b = *(const float4*)(Was + DD + cb + 4);
    float4 wd0a = *(const float4*)(Wad + cb);
    float4 wd0b = *(const float4*)(Wad + cb + 4);
    float4 wd1a = *(const float4*)(Wad + DD + cb);
    float4 wd1b = *(const float4*)(Wad + DD + cb + 4);

    for (int n = warp; n < NN; n += nwarps) {
        const float* fp = feat + (size_t)n * DD + cb;
        float4 x0 = *(const float4*)fp;
        float4 x1 = *(const float4*)(fp + 4);
        float s0 = dot8(x0, x1, ws0a, ws0b);
        float s1 = dot8(x0, x1, ws1a, ws1b);
        float d0 = dot8(x0, x1, wd0a, wd0b);
        float d1 = dot8(x0, x1, wd1a, wd1b);
#pragma unroll
        for (int off = 16; off > 0; off >>= 1) {
            s0 += __shfl_xor_sync(0xffffffff, s0, off);
            s1 += __shfl_xor_sync(0xffffffff, s1, off);
            d0 += __shfl_xor_sync(0xffffffff, d0, off);
            d1 += __shfl_xor_sync(0xffffffff, d1, off);
        }
        if (lane == 0) {
            g_asrc[n] = make_float2(s0, s1);
            g_adst[n] = make_float2(d0, d1);
        }
    }
}

// ---------------- fused edge: logit + leaky + exp -> CSR slot ---------------
__global__ void edge_kernel(const float* __restrict__ fe,
                            const int* __restrict__ es,
                            const int* __restrict__ ed,
                            const float* __restrict__ Wae) {
    int i = blockIdx.x * blockDim.x + threadIdx.x;
    if (i >= EE) return;

    float4 x0 = *(const float4*)(fe + (size_t)i * DE);
    float4 x1 = *(const float4*)(fe + (size_t)i * DE + 4);

    float ae0 = x0.x * __ldg(Wae + 0) + x0.y * __ldg(Wae + 1) +
                x0.z * __ldg(Wae + 2) + x0.w * __ldg(Wae + 3) +
                x1.x * __ldg(Wae + 4) + x1.y * __ldg(Wae + 5) +
                x1.z * __ldg(Wae + 6) + x1.w * __ldg(Wae + 7);
    float ae1 = x0.x * __ldg(Wae + 8)  + x0.y * __ldg(Wae + 9) +
                x0.z * __ldg(Wae + 10) + x0.w * __ldg(Wae + 11) +
                x1.x * __ldg(Wae + 12) + x1.y * __ldg(Wae + 13) +
                x1.z * __ldg(Wae + 14) + x1.w * __ldg(Wae + 15);

    int s = es[i], d = ed[i];
    float2 as = g_asrc[s];
    float2 ad = g_adst[d];
    float e0 = as.x + ad.x + ae0;
    float e1 = as.y + ad.y + ae1;
    e0 = (e0 >= 0.f) ? e0 : NEG_SLOPE * e0;
    e1 = (e1 >= 0.f) ? e1 : NEG_SLOPE * e1;
    g_ep[g_epos[i]] = make_float2(__expf(e0), __expf(e1));
}

// ---------------- pull aggregation: warp per dst node ------------------------
__global__ void agg_kernel() {
    int warp = (blockIdx.x * blockDim.x + threadIdx.x) >> 5;
    if (warp >= NN) return;
    int lane = threadIdx.x & 31;

    int row = g_off[warp];
    int end = g_off[warp + 1];

    // softmax denominator (both heads)
    float z0 = 0.f, z1 = 0.f;
    for (int j = row + lane; j < end; j += 32) {
        float2 e = g_ep[j];
        z0 += e.x;
        z1 += e.y;
    }
#pragma unroll
    for (int off = 16; off > 0; off >>= 1) {
        z0 += __shfl_xor_sync(0xffffffff, z0, off);
        z1 += __shfl_xor_sync(0xffffffff, z1, off);
    }
    float invz = __fdividef(1.f, (lane < 16) ? z0 : z1);

    const int elem = lane * 4;   // lanes 0..15 head0, 16..31 head1
    float a0 = 0.f, a1 = 0.f, a2 = 0.f, a3 = 0.f;

    int j = row;
    for (; j + 2 <= end; j += 2) {
        float2 e0 = g_ep[j];
        float2 e1 = g_ep[j + 1];
        int s0 = g_psrc[j];
        int s1 = g_psrc[j + 1];
        float c0 = ((lane < 16) ? e0.x : e0.y) * invz;
        float c1 = ((lane < 16) ? e1.x : e1.y) * invz;
        const __half2* p0 = (const __half2*)(g_hsrc_h + (size_t)s0 * HF + elem);
        const __half2* p1 = (const __half2*)(g_hsrc_h + (size_t)s1 * HF + elem);
        __half2 u0 = p0[0], u1 = p0[1];
        __half2 v0 = p1[0], v1 = p1[1];
        float2 fu0 = __half22float2(u0), fu1 = __half22float2(u1);
        float2 fv0 = __half22float2(v0), fv1 = __half22float2(v1);
        a0 = fmaf(fu0.x, c0, a0); a1 = fmaf(fu0.y, c0, a1);
        a2 = fmaf(fu1.x, c0, a2); a3 = fmaf(fu1.y, c0, a3);
        a0 = fmaf(fv0.x, c1, a0); a1 = fmaf(fv0.y, c1, a1);
        a2 = fmaf(fv1.x, c1, a2); a3 = fmaf(fv1.y, c1, a3);
    }
    if (j < end) {
        float2 e0 = g_ep[j];
        int s0 = g_psrc[j];
        float c0 = ((lane < 16) ? e0.x : e0.y) * invz;
        const __half2* p0 = (const __half2*)(g_hsrc_h + (size_t)s0 * HF + elem);
        __half2 u0 = p0[0], u1 = p0[1];
        float2 fu0 = __half22float2(u0), fu1 = __half22float2(u1);
        a0 = fmaf(fu0.x, c0, a0); a1 = fmaf(fu0.y, c0, a1);
        a2 = fmaf(fu1.x, c0, a2); a3 = fmaf(fu1.y, c0, a3);
    }
    *(float4*)(g_rst + (size_t)warp * HF + elem) = make_float4(a0, a1, a2, a3);
}

// ---------------- launch -----------------------------------------------------
extern "C" void kernel_launch(void* const* d_in, const int* in_sizes, int n_in,
                              void* d_out, int out_size) {
    const float* feat_src    = (const float*)d_in[0];
    const float* feat_edge   = (const float*)d_in[1];
    const int*   edge_src    = (const int*)d_in[2];
    const int*   edge_dst    = (const int*)d_in[3];
    const float* W_src       = (const float*)d_in[4];
    const float* W_dst       = (const float*)d_in[5];
    const float* b_dst       = (const float*)d_in[6];
    const float* W_attn_src  = (const float*)d_in[7];
    const float* W_attn_dst  = (const float*)d_in[8];
    const float* W_attn_edge = (const float*)d_in[9];
    const float* W_ngnn      = (const float*)d_in[10];
    const float* b_ngnn      = (const float*)d_in[11];
    float* out = (float*)d_out;

    __half* hsrc_h; cudaGetSymbolAddress((void**)&hsrc_h, g_hsrc_h);
    float* hdst;    cudaGetSymbolAddress((void**)&hdst, g_hdst);
    float* rst;     cudaGetSymbolAddress((void**)&rst,  g_rst);
    int* cnt;       cudaGetSymbolAddress((void**)&cnt,  g_cnt);

    // CSR build
    cudaMemsetAsync(cnt, 0, NN * sizeof(int));
    hist_kernel<<<(EE + 255) / 256, 256>>>(edge_dst);
    scan_kernel<<<1, 1024>>>();
    scatter_kernel<<<(EE + 255) / 256, 256>>>(edge_src, edge_dst);

    // node GEMMs: h_src (fp16 out) & h_dst (fp32) in one launch
    gemm_kernel<<<dim3(2, (NN + 127) / 128), 256>>>(
        feat_src, W_src, W_dst, nullptr, b_dst, nullptr,
        nullptr, hdst, hsrc_h, NN, DD, 0);

    // per-node attention logits
    attn_kernel<<<1024, 256>>>(feat_src, W_attn_src, W_attn_dst);

    // fused edge logits + exp -> CSR slots
    edge_kernel<<<(EE + 255) / 256, 256>>>(feat_edge, edge_src, edge_dst,
                                           W_attn_edge);

    // pull aggregation (softmax + weighted sum), warp per dst
    agg_kernel<<<(NN * 32 + 255) / 256, 256>>>();

    // NGNN GEMM + ReLU + bias + residual -> out
    gemm_kernel<<<dim3(1, (NN + 127) / 128), 256>>>(
        rst, W_ngnn, W_ngnn, b_ngnn, b_ngnn, hdst,
        out, out, nullptr, NN, HF, 1);
}

// round 4
// speedup vs baseline: 1.3907x; 1.3907x over previous
#include <cuda_runtime.h>
#include <cuda_fp16.h>
#include <mma.h>
#include <math.h>
#include <stdint.h>

using namespace nvcuda;

#define NN 100000
#define EE 1600000
#define DD 256
#define DE 8
#define HF 128
#define NEG_SLOPE 0.2f

// ---------------- scratch (device globals) ----------------------------------
__device__ __half  g_feat_h[(size_t)NN * DD];   // fp16 feat_src
__device__ __half  g_wsrc_h[HF * DD];
__device__ __half  g_wdst_h[HF * DD];
__device__ __half  g_wngnn_h[HF * HF];
__device__ __half  g_hsrc_h[(size_t)NN * HF];   // fp16 h_src (gather payload)
__device__ float   g_hdst[(size_t)NN * HF];
__device__ __half  g_rst_h[(size_t)NN * HF];    // fp16 aggregation result
__device__ float2  g_asrc[NN];
__device__ float2  g_adst[NN];
__device__ float2  g_ep  [EE];                  // exp(e) in CSR order
__device__ int     g_cnt [NN];
__device__ int     g_off [NN + 1];
__device__ int     g_cur [NN];
__device__ int     g_psrc[EE];                  // src node per CSR slot
__device__ int     g_epos[EE];                  // edge i -> CSR slot

// ---------------- fp32 -> fp16 convert ---------------------------------------
__global__ void f2h_kernel(const float* __restrict__ src,
                           __half* __restrict__ dst, int n8) {
    int i = blockIdx.x * blockDim.x + threadIdx.x;
    if (i >= n8) return;
    const float4* s = (const float4*)(src + (size_t)i * 8);
    float4 a = s[0], b = s[1];
    __half2 h[4] = {__floats2half2_rn(a.x, a.y), __floats2half2_rn(a.z, a.w),
                    __floats2half2_rn(b.x, b.y), __floats2half2_rn(b.z, b.w)};
    *(uint4*)(dst + (size_t)i * 8) = *(uint4*)h;
}

// ---------------- CSR build --------------------------------------------------
__global__ void hist_kernel(const int* __restrict__ ed) {
    int i = blockIdx.x * blockDim.x + threadIdx.x;
    if (i < EE) atomicAdd(&g_cnt[ed[i]], 1);
}

__global__ void scan_kernel() {
    __shared__ int ssum[1024];
    int t = threadIdx.x;
    const int CH = (NN + 1023) / 1024;
    int beg = t * CH;
    int end = min(beg + CH, NN);
    int s = 0;
    for (int i = beg; i < end; i++) s += g_cnt[i];
    ssum[t] = s;
    __syncthreads();
#pragma unroll
    for (int off = 1; off < 1024; off <<= 1) {
        int add = (t >= off) ? ssum[t - off] : 0;
        __syncthreads();
        ssum[t] += add;
        __syncthreads();
    }
    int base = (t == 0) ? 0 : ssum[t - 1];
    for (int i = beg; i < end; i++) {
        g_off[i] = base;
        g_cur[i] = base;
        base += g_cnt[i];
    }
    if (t == 1023) g_off[NN] = EE;
}

__global__ void scatter_kernel(const int* __restrict__ es,
                               const int* __restrict__ ed) {
    int i = blockIdx.x * blockDim.x + threadIdx.x;
    if (i >= EE) return;
    int pos = atomicAdd(&g_cur[ed[i]], 1);
    g_psrc[pos] = es[i];
    g_epos[i] = pos;
}

// ---------------- tensor-core GEMM: C[*,128] = A[M,K] @ B[128,K]^T ----------
// 128x128x32 CTA tile, 8 warps (4 M x 2 N), warp tile 32x64 (2x4 wmma frags)
// blockIdx.x selects {B0,bias0,C0} / {B1,bias1,C1f}
// mode 0: C = acc (+bias)     mode 1: C = relu(acc+bias) + add
// blockIdx.x==0 && C0h!=null -> fp16 output
#define LDA 40
#define LDC 132
__global__ void __launch_bounds__(256)
gemm_h_kernel(const __half* __restrict__ A,
              const __half* __restrict__ B0, const __half* __restrict__ B1,
              const float* __restrict__ bias0, const float* __restrict__ bias1,
              const float* __restrict__ add,
              float* __restrict__ C0f, float* __restrict__ C1f,
              __half* __restrict__ C0h,
              int M, int K, int mode) {
    extern __shared__ char dynsm[];
    __half* As = (__half*)dynsm;                       // [128][40]
    __half* Bs = (__half*)(dynsm + 128 * LDA * 2);     // [128][40]
    float*  Cs = (float*)dynsm;                        // [128][132] (reused)

    const __half* B    = (blockIdx.x == 0) ? B0 : B1;
    const float*  bias = (blockIdx.x == 0) ? bias0 : bias1;
    bool h_out = (blockIdx.x == 0) && (C0h != nullptr);

    int bm = blockIdx.y * 128;
    int t  = threadIdx.x;
    int w  = t >> 5;
    int wm = w & 3;           // warp row (0..3) -> 32 rows
    int wn = w >> 2;          // warp col (0..1) -> 64 cols

    wmma::fragment<wmma::accumulator, 16, 16, 16, float> cf[2][4];
#pragma unroll
    for (int i = 0; i < 2; i++)
#pragma unroll
        for (int j = 0; j < 4; j++) wmma::fill_fragment(cf[i][j], 0.0f);

    int lr = t >> 1;              // load row 0..127
    int lh = (t & 1) * 16;        // half-row chunk: 16 halves

    for (int kt = 0; kt < K; kt += 32) {
        // A tile
        {
            int arow = bm + lr;
            uint4 v0 = make_uint4(0, 0, 0, 0), v1 = v0;
            if (arow < M) {
                const __half* ap = A + (size_t)arow * K + kt + lh;
                v0 = *(const uint4*)ap;
                v1 = *(const uint4*)(ap + 8);
            }
            *(uint4*)&As[lr * LDA + lh] = v0;
            *(uint4*)&As[lr * LDA + lh + 8] = v1;
        }
        // B tile (always 128 full rows)
        {
            const __half* bp = B + (size_t)lr * K + kt + lh;
            *(uint4*)&Bs[lr * LDA + lh] = *(const uint4*)bp;
            *(uint4*)&Bs[lr * LDA + lh + 8] = *(const uint4*)(bp + 8);
        }
        __syncthreads();

#pragma unroll
        for (int ks = 0; ks < 32; ks += 16) {
            wmma::fragment<wmma::matrix_a, 16, 16, 16, __half, wmma::row_major> af[2];
            wmma::fragment<wmma::matrix_b, 16, 16, 16, __half, wmma::col_major> bf[4];
#pragma unroll
            for (int i = 0; i < 2; i++)
                wmma::load_matrix_sync(af[i], &As[(wm * 32 + i * 16) * LDA + ks], LDA);
#pragma unroll
            for (int j = 0; j < 4; j++)
                wmma::load_matrix_sync(bf[j], &Bs[(wn * 64 + j * 16) * LDA + ks], LDA);
#pragma unroll
            for (int i = 0; i < 2; i++)
#pragma unroll
                for (int j = 0; j < 4; j++)
                    wmma::mma_sync(cf[i][j], af[i], bf[j], cf[i][j]);
        }
        __syncthreads();
    }

    // stage C through smem (reuses As/Bs region)
#pragma unroll
    for (int i = 0; i < 2; i++)
#pragma unroll
        for (int j = 0; j < 4; j++)
            wmma::store_matrix_sync(&Cs[(wm * 32 + i * 16) * LDC + wn * 64 + j * 16],
                                    cf[i][j], LDC, wmma::mem_row_major);
    __syncthreads();

    // epilogue: thread handles row r = t>>1, 64 cols at (t&1)*64
    {
        int r = t >> 1;
        int cb = (t & 1) * 64;
        int row = bm + r;
        if (row < M) {
#pragma unroll
            for (int j = 0; j < 64; j += 4) {
                float4 v = *(float4*)&Cs[r * LDC + cb + j];
                if (bias) {
                    float4 b = *(const float4*)(bias + cb + j);
                    v.x += b.x; v.y += b.y; v.z += b.z; v.w += b.w;
                }
                if (mode == 1) {
                    float4 rs = *(const float4*)(add + (size_t)row * HF + cb + j);
                    v.x = fmaxf(v.x, 0.f) + rs.x;
                    v.y = fmaxf(v.y, 0.f) + rs.y;
                    v.z = fmaxf(v.z, 0.f) + rs.z;
                    v.w = fmaxf(v.w, 0.f) + rs.w;
                }
                if (h_out) {
                    __half2 p[2] = {__floats2half2_rn(v.x, v.y),
                                    __floats2half2_rn(v.z, v.w)};
                    *(uint2*)(C0h + (size_t)row * HF + cb + j) = *(uint2*)p;
                } else {
                    float* Cf = (blockIdx.x == 0) ? C0f : C1f;
                    *(float4*)(Cf + (size_t)row * HF + cb + j) = v;
                }
            }
        }
    }
}

// ---------------- per-node attention logits ---------------------------------
static __device__ __forceinline__ float dot8(float4 x0, float4 x1,
                                             float4 w0, float4 w1) {
    float s = x0.x * w0.x;
    s = fmaf(x0.y, w0.y, s); s = fmaf(x0.z, w0.z, s); s = fmaf(x0.w, w0.w, s);
    s = fmaf(x1.x, w1.x, s); s = fmaf(x1.y, w1.y, s);
    s = fmaf(x1.z, w1.z, s); s = fmaf(x1.w, w1.w, s);
    return s;
}

__global__ void attn_kernel(const float* __restrict__ feat,
                            const float* __restrict__ Was,
                            const float* __restrict__ Wad) {
    int lane = threadIdx.x & 31;
    int warp = (blockIdx.x * blockDim.x + threadIdx.x) >> 5;
    int nwarps = (gridDim.x * blockDim.x) >> 5;
    int cb = lane * 8;

    float4 ws0a = *(const float4*)(Was + cb);
    float4 ws0b = *(const float4*)(Was + cb + 4);
    float4 ws1a = *(const float4*)(Was + DD + cb);
    float4 ws1b = *(const float4*)(Was + DD + cb + 4);
    float4 wd0a = *(const float4*)(Wad + cb);
    float4 wd0b = *(const float4*)(Wad + cb + 4);
    float4 wd1a = *(const float4*)(Wad + DD + cb);
    float4 wd1b = *(const float4*)(Wad + DD + cb + 4);

    for (int n = warp; n < NN; n += nwarps) {
        const float* fp = feat + (size_t)n * DD + cb;
        float4 x0 = *(const float4*)fp;
        float4 x1 = *(const float4*)(fp + 4);
        float s0 = dot8(x0, x1, ws0a, ws0b);
        float s1 = dot8(x0, x1, ws1a, ws1b);
        float d0 = dot8(x0, x1, wd0a, wd0b);
        float d1 = dot8(x0, x1, wd1a, wd1b);
#pragma unroll
        for (int off = 16; off > 0; off >>= 1) {
            s0 += __shfl_xor_sync(0xffffffff, s0, off);
            s1 += __shfl_xor_sync(0xffffffff, s1, off);
            d0 += __shfl_xor_sync(0xffffffff, d0, off);
            d1 += __shfl_xor_sync(0xffffffff, d1, off);
        }
        if (lane == 0) {
            g_asrc[n] = make_float2(s0, s1);
            g_adst[n] = make_float2(d0, d1);
        }
    }
}

// ---------------- fused edge: logit + leaky + exp -> CSR slot ---------------
__global__ void edge_kernel(const float* __restrict__ fe,
                            const int* __restrict__ es,
                            const int* __restrict__ ed,
                            const float* __restrict__ Wae) {
    int i = blockIdx.x * blockDim.x + threadIdx.x;
    if (i >= EE) return;

    float4 x0 = *(const float4*)(fe + (size_t)i * DE);
    float4 x1 = *(const float4*)(fe + (size_t)i * DE + 4);

    float ae0 = x0.x * __ldg(Wae + 0) + x0.y * __ldg(Wae + 1) +
                x0.z * __ldg(Wae + 2) + x0.w * __ldg(Wae + 3) +
                x1.x * __ldg(Wae + 4) + x1.y * __ldg(Wae + 5) +
                x1.z * __ldg(Wae + 6) + x1.w * __ldg(Wae + 7);
    float ae1 = x0.x * __ldg(Wae + 8)  + x0.y * __ldg(Wae + 9) +
                x0.z * __ldg(Wae + 10) + x0.w * __ldg(Wae + 11) +
                x1.x * __ldg(Wae + 12) + x1.y * __ldg(Wae + 13) +
                x1.z * __ldg(Wae + 14) + x1.w * __ldg(Wae + 15);

    int s = es[i], d = ed[i];
    float2 as = g_asrc[s];
    float2 ad = g_adst[d];
    float e0 = as.x + ad.x + ae0;
    float e1 = as.y + ad.y + ae1;
    e0 = (e0 >= 0.f) ? e0 : NEG_SLOPE * e0;
    e1 = (e1 >= 0.f) ? e1 : NEG_SLOPE * e1;
    g_ep[g_epos[i]] = make_float2(__expf(e0), __expf(e1));
}

// ---------------- pull aggregation: warp per dst node ------------------------
__global__ void agg_kernel() {
    int warp = (blockIdx.x * blockDim.x + threadIdx.x) >> 5;
    if (warp >= NN) return;
    int lane = threadIdx.x & 31;

    int row = g_off[warp];
    int end = g_off[warp + 1];

    float z0 = 0.f, z1 = 0.f;
    for (int j = row + lane; j < end; j += 32) {
        float2 e = g_ep[j];
        z0 += e.x;
        z1 += e.y;
    }
#pragma unroll
    for (int off = 16; off > 0; off >>= 1) {
        z0 += __shfl_xor_sync(0xffffffff, z0, off);
        z1 += __shfl_xor_sync(0xffffffff, z1, off);
    }
    float invz = __fdividef(1.f, (lane < 16) ? z0 : z1);

    const int elem = lane * 4;   // lanes 0..15 head0, 16..31 head1
    float a0 = 0.f, a1 = 0.f, a2 = 0.f, a3 = 0.f;

    int j = row;
    for (; j + 2 <= end; j += 2) {
        float2 e0 = g_ep[j];
        float2 e1 = g_ep[j + 1];
        int s0 = g_psrc[j];
        int s1 = g_psrc[j + 1];
        float c0 = ((lane < 16) ? e0.x : e0.y) * invz;
        float c1 = ((lane < 16) ? e1.x : e1.y) * invz;
        const __half2* p0 = (const __half2*)(g_hsrc_h + (size_t)s0 * HF + elem);
        const __half2* p1 = (const __half2*)(g_hsrc_h + (size_t)s1 * HF + elem);
        __half2 u0 = p0[0], u1 = p0[1];
        __half2 v0 = p1[0], v1 = p1[1];
        float2 fu0 = __half22float2(u0), fu1 = __half22float2(u1);
        float2 fv0 = __half22float2(v0), fv1 = __half22float2(v1);
        a0 = fmaf(fu0.x, c0, a0); a1 = fmaf(fu0.y, c0, a1);
        a2 = fmaf(fu1.x, c0, a2); a3 = fmaf(fu1.y, c0, a3);
        a0 = fmaf(fv0.x, c1, a0); a1 = fmaf(fv0.y, c1, a1);
        a2 = fmaf(fv1.x, c1, a2); a3 = fmaf(fv1.y, c1, a3);
    }
    if (j < end) {
        float2 e0 = g_ep[j];
        int s0 = g_psrc[j];
        float c0 = ((lane < 16) ? e0.x : e0.y) * invz;
        const __half2* p0 = (const __half2*)(g_hsrc_h + (size_t)s0 * HF + elem);
        __half2 u0 = p0[0], u1 = p0[1];
        float2 fu0 = __half22float2(u0), fu1 = __half22float2(u1);
        a0 = fmaf(fu0.x, c0, a0); a1 = fmaf(fu0.y, c0, a1);
        a2 = fmaf(fu1.x, c0, a2); a3 = fmaf(fu1.y, c0, a3);
    }
    __half2 hh[2] = {__floats2half2_rn(a0, a1), __floats2half2_rn(a2, a3)};
    *(uint2*)(g_rst_h + (size_t)warp * HF + elem) = *(uint2*)hh;
}

// ---------------- launch -----------------------------------------------------
extern "C" void kernel_launch(void* const* d_in, const int* in_sizes, int n_in,
                              void* d_out, int out_size) {
    const float* feat_src    = (const float*)d_in[0];
    const float* feat_edge   = (const float*)d_in[1];
    const int*   edge_src    = (const int*)d_in[2];
    const int*   edge_dst    = (const int*)d_in[3];
    const float* W_src       = (const float*)d_in[4];
    const float* W_dst       = (const float*)d_in[5];
    const float* b_dst       = (const float*)d_in[6];
    const float* W_attn_src  = (const float*)d_in[7];
    const float* W_attn_dst  = (const float*)d_in[8];
    const float* W_attn_edge = (const float*)d_in[9];
    const float* W_ngnn      = (const float*)d_in[10];
    const float* b_ngnn      = (const float*)d_in[11];
    float* out = (float*)d_out;

    __half* feat_h;  cudaGetSymbolAddress((void**)&feat_h,  g_feat_h);
    __half* wsrc_h;  cudaGetSymbolAddress((void**)&wsrc_h,  g_wsrc_h);
    __half* wdst_h;  cudaGetSymbolAddress((void**)&wdst_h,  g_wdst_h);
    __half* wngnn_h; cudaGetSymbolAddress((void**)&wngnn_h, g_wngnn_h);
    __half* hsrc_h;  cudaGetSymbolAddress((void**)&hsrc_h,  g_hsrc_h);
    float*  hdst;    cudaGetSymbolAddress((void**)&hdst,    g_hdst);
    __half* rst_h;   cudaGetSymbolAddress((void**)&rst_h,   g_rst_h);
    int*    cnt;     cudaGetSymbolAddress((void**)&cnt,     g_cnt);

    static bool attr_set = false;
    if (!attr_set) {
        cudaFuncSetAttribute(gemm_h_kernel,
                             cudaFuncAttributeMaxDynamicSharedMemorySize,
                             128 * LDC * 4);
        attr_set = true;
    }
    const int dynsm = 128 * LDC * 4;   // 67584 B (C staging dominates)

    // CSR build
    cudaMemsetAsync(cnt, 0, NN * sizeof(int));
    hist_kernel<<<(EE + 255) / 256, 256>>>(edge_dst);
    scan_kernel<<<1, 1024>>>();
    scatter_kernel<<<(EE + 255) / 256, 256>>>(edge_src, edge_dst);

    // fp16 conversions
    f2h_kernel<<<(NN * DD / 8 + 255) / 256, 256>>>(feat_src, feat_h, NN * DD / 8);
    f2h_kernel<<<(HF * DD / 8 + 255) / 256, 256>>>(W_src, wsrc_h, HF * DD / 8);
    f2h_kernel<<<(HF * DD / 8 + 255) / 256, 256>>>(W_dst, wdst_h, HF * DD / 8);
    f2h_kernel<<<(HF * HF / 8 + 255) / 256, 256>>>(W_ngnn, wngnn_h, HF * HF / 8);

    // node GEMMs: h_src (fp16 out) & h_dst (fp32 + bias) in one launch
    gemm_h_kernel<<<dim3(2, (NN + 127) / 128), 256, dynsm>>>(
        feat_h, wsrc_h, wdst_h, nullptr, b_dst, nullptr,
        nullptr, hdst, hsrc_h, NN, DD, 0);

    // per-node attention logits
    attn_kernel<<<1024, 256>>>(feat_src, W_attn_src, W_attn_dst);

    // fused edge logits + exp -> CSR slots
    edge_kernel<<<(EE + 255) / 256, 256>>>(feat_edge, edge_src, edge_dst,
                                           W_attn_edge);

    // pull aggregation (softmax + weighted sum), warp per dst
    agg_kernel<<<(NN * 32 + 255) / 256, 256>>>();

    // NGNN GEMM + ReLU + bias + residual -> out
    gemm_h_kernel<<<dim3(1, (NN + 127) / 128), 256, dynsm>>>(
        rst_h, wngnn_h, wngnn_h, b_ngnn, b_ngnn, hdst,
        out, out, nullptr, NN, HF, 1);
}

// round 5
// speedup vs baseline: 1.4781x; 1.0629x over previous
#include <cuda_runtime.h>
#include <cuda_fp16.h>
#include <mma.h>
#include <math.h>
#include <stdint.h>

using namespace nvcuda;

#define NN 100000
#define EE 1600000
#define DD 256
#define DE 8
#define HF 128
#define NEG_SLOPE 0.2f

// ---------------- scratch (device globals) ----------------------------------
__device__ __half  g_feat_h[(size_t)NN * DD];   // fp16 feat_src
__device__ __half  g_wsrc_h[HF * DD];
__device__ __half  g_wdst_h[HF * DD];
__device__ __half  g_wngnn_h[HF * HF];
__device__ __half  g_hsrc_h[(size_t)NN * HF];   // fp16 h_src (gather payload)
__device__ float   g_hdst[(size_t)NN * HF];
__device__ __half  g_rst_h[(size_t)NN * HF];    // fp16 aggregation result
__device__ float2  g_asrc[NN];
__device__ float2  g_adst[NN];
__device__ float2  g_ep  [EE];                  // exp(e) in CSR order
__device__ int     g_cnt [NN];
__device__ int     g_off [NN + 1];
__device__ int     g_cur [NN];
__device__ int     g_psrc[EE];                  // src node per CSR slot

// ---------------- fused: feat fp32->fp16 + attention logits ------------------
static __device__ __forceinline__ float dot8(float4 x0, float4 x1,
                                             float4 w0, float4 w1) {
    float s = x0.x * w0.x;
    s = fmaf(x0.y, w0.y, s); s = fmaf(x0.z, w0.z, s); s = fmaf(x0.w, w0.w, s);
    s = fmaf(x1.x, w1.x, s); s = fmaf(x1.y, w1.y, s);
    s = fmaf(x1.z, w1.z, s); s = fmaf(x1.w, w1.w, s);
    return s;
}

__global__ void feat_attn_kernel(const float* __restrict__ feat,
                                 const float* __restrict__ Was,
                                 const float* __restrict__ Wad) {
    int lane = threadIdx.x & 31;
    int warp = (blockIdx.x * blockDim.x + threadIdx.x) >> 5;
    int nwarps = (gridDim.x * blockDim.x) >> 5;
    int cb = lane * 8;

    float4 ws0a = *(const float4*)(Was + cb);
    float4 ws0b = *(const float4*)(Was + cb + 4);
    float4 ws1a = *(const float4*)(Was + DD + cb);
    float4 ws1b = *(const float4*)(Was + DD + cb + 4);
    float4 wd0a = *(const float4*)(Wad + cb);
    float4 wd0b = *(const float4*)(Wad + cb + 4);
    float4 wd1a = *(const float4*)(Wad + DD + cb);
    float4 wd1b = *(const float4*)(Wad + DD + cb + 4);

    for (int n = warp; n < NN; n += nwarps) {
        const float* fp = feat + (size_t)n * DD + cb;
        float4 x0 = *(const float4*)fp;
        float4 x1 = *(const float4*)(fp + 4);

        // fp16 conversion + store
        __half2 h[4] = {__floats2half2_rn(x0.x, x0.y),
                        __floats2half2_rn(x0.z, x0.w),
                        __floats2half2_rn(x1.x, x1.y),
                        __floats2half2_rn(x1.z, x1.w)};
        *(uint4*)(g_feat_h + (size_t)n * DD + cb) = *(uint4*)h;

        // attention dots
        float s0 = dot8(x0, x1, ws0a, ws0b);
        float s1 = dot8(x0, x1, ws1a, ws1b);
        float d0 = dot8(x0, x1, wd0a, wd0b);
        float d1 = dot8(x0, x1, wd1a, wd1b);
#pragma unroll
        for (int off = 16; off > 0; off >>= 1) {
            s0 += __shfl_xor_sync(0xffffffff, s0, off);
            s1 += __shfl_xor_sync(0xffffffff, s1, off);
            d0 += __shfl_xor_sync(0xffffffff, d0, off);
            d1 += __shfl_xor_sync(0xffffffff, d1, off);
        }
        if (lane == 0) {
            g_asrc[n] = make_float2(s0, s1);
            g_adst[n] = make_float2(d0, d1);
        }
    }
}

// ---------------- weight conversions (one launch) ----------------------------
__global__ void wconv_kernel(const float* __restrict__ Wsrc,
                             const float* __restrict__ Wdst,
                             const float* __restrict__ Wngnn) {
    int i = blockIdx.x * blockDim.x + threadIdx.x;
    const int n1 = HF * DD / 8, n2 = 2 * n1, n3 = n2 + HF * HF / 8;
    const float* src;
    __half* dst;
    int k;
    if (i < n1)      { src = Wsrc;  dst = g_wsrc_h;  k = i; }
    else if (i < n2) { src = Wdst;  dst = g_wdst_h;  k = i - n1; }
    else if (i < n3) { src = Wngnn; dst = g_wngnn_h; k = i - n2; }
    else return;
    const float4* s = (const float4*)(src + (size_t)k * 8);
    float4 a = s[0], b = s[1];
    __half2 h[4] = {__floats2half2_rn(a.x, a.y), __floats2half2_rn(a.z, a.w),
                    __floats2half2_rn(b.x, b.y), __floats2half2_rn(b.z, b.w)};
    *(uint4*)(dst + (size_t)k * 8) = *(uint4*)h;
}

// ---------------- CSR build --------------------------------------------------
__global__ void hist_kernel(const int* __restrict__ ed) {
    int i = blockIdx.x * blockDim.x + threadIdx.x;
    if (i < EE) atomicAdd(&g_cnt[ed[i]], 1);
}

__global__ void scan_kernel() {
    __shared__ int ssum[1024];
    int t = threadIdx.x;
    const int CH = (NN + 1023) / 1024;
    int beg = t * CH;
    int end = min(beg + CH, NN);
    int s = 0;
    for (int i = beg; i < end; i++) s += g_cnt[i];
    ssum[t] = s;
    __syncthreads();
#pragma unroll
    for (int off = 1; off < 1024; off <<= 1) {
        int add = (t >= off) ? ssum[t - off] : 0;
        __syncthreads();
        ssum[t] += add;
        __syncthreads();
    }
    int base = (t == 0) ? 0 : ssum[t - 1];
    for (int i = beg; i < end; i++) {
        g_off[i] = base;
        g_cur[i] = base;
        base += g_cnt[i];
    }
    if (t == 1023) g_off[NN] = EE;
}

// ---------------- fused: CSR scatter + edge logit + leaky + exp --------------
__global__ void scatter_edge_kernel(const int* __restrict__ es,
                                    const int* __restrict__ ed,
                                    const float* __restrict__ fe,
                                    const float* __restrict__ Wae) {
    int i = blockIdx.x * blockDim.x + threadIdx.x;
    if (i >= EE) return;

    int s = es[i], d = ed[i];
    int pos = atomicAdd(&g_cur[d], 1);
    g_psrc[pos] = s;

    float4 x0 = *(const float4*)(fe + (size_t)i * DE);
    float4 x1 = *(const float4*)(fe + (size_t)i * DE + 4);

    float ae0 = x0.x * __ldg(Wae + 0) + x0.y * __ldg(Wae + 1) +
                x0.z * __ldg(Wae + 2) + x0.w * __ldg(Wae + 3) +
                x1.x * __ldg(Wae + 4) + x1.y * __ldg(Wae + 5) +
                x1.z * __ldg(Wae + 6) + x1.w * __ldg(Wae + 7);
    float ae1 = x0.x * __ldg(Wae + 8)  + x0.y * __ldg(Wae + 9) +
                x0.z * __ldg(Wae + 10) + x0.w * __ldg(Wae + 11) +
                x1.x * __ldg(Wae + 12) + x1.y * __ldg(Wae + 13) +
                x1.z * __ldg(Wae + 14) + x1.w * __ldg(Wae + 15);

    float2 as = g_asrc[s];
    float2 ad = g_adst[d];
    float e0 = as.x + ad.x + ae0;
    float e1 = as.y + ad.y + ae1;
    e0 = (e0 >= 0.f) ? e0 : NEG_SLOPE * e0;
    e1 = (e1 >= 0.f) ? e1 : NEG_SLOPE * e1;
    g_ep[pos] = make_float2(__expf(e0), __expf(e1));
}

// ---------------- tensor-core GEMM: C[*,128] = A[M,K] @ B[128,K]^T ----------
#define LDA 40
#define LDC 132
__global__ void __launch_bounds__(256)
gemm_h_kernel(const __half* __restrict__ A,
              const __half* __restrict__ B0, const __half* __restrict__ B1,
              const float* __restrict__ bias0, const float* __restrict__ bias1,
              const float* __restrict__ add,
              float* __restrict__ C0f, float* __restrict__ C1f,
              __half* __restrict__ C0h,
              int M, int K, int mode) {
    extern __shared__ char dynsm[];
    __half* As = (__half*)dynsm;                       // [128][40]
    __half* Bs = (__half*)(dynsm + 128 * LDA * 2);     // [128][40]
    float*  Cs = (float*)dynsm;                        // [128][132] (reused)

    const __half* B    = (blockIdx.x == 0) ? B0 : B1;
    const float*  bias = (blockIdx.x == 0) ? bias0 : bias1;
    bool h_out = (blockIdx.x == 0) && (C0h != nullptr);

    int bm = blockIdx.y * 128;
    int t  = threadIdx.x;
    int w  = t >> 5;
    int wm = w & 3;
    int wn = w >> 2;

    wmma::fragment<wmma::accumulator, 16, 16, 16, float> cf[2][4];
#pragma unroll
    for (int i = 0; i < 2; i++)
#pragma unroll
        for (int j = 0; j < 4; j++) wmma::fill_fragment(cf[i][j], 0.0f);

    int lr = t >> 1;
    int lh = (t & 1) * 16;

    for (int kt = 0; kt < K; kt += 32) {
        {
            int arow = bm + lr;
            uint4 v0 = make_uint4(0, 0, 0, 0), v1 = v0;
            if (arow < M) {
                const __half* ap = A + (size_t)arow * K + kt + lh;
                v0 = *(const uint4*)ap;
                v1 = *(const uint4*)(ap + 8);
            }
            *(uint4*)&As[lr * LDA + lh] = v0;
            *(uint4*)&As[lr * LDA + lh + 8] = v1;
        }
        {
            const __half* bp = B + (size_t)lr * K + kt + lh;
            *(uint4*)&Bs[lr * LDA + lh] = *(const uint4*)bp;
            *(uint4*)&Bs[lr * LDA + lh + 8] = *(const uint4*)(bp + 8);
        }
        __syncthreads();

#pragma unroll
        for (int ks = 0; ks < 32; ks += 16) {
            wmma::fragment<wmma::matrix_a, 16, 16, 16, __half, wmma::row_major> af[2];
            wmma::fragment<wmma::matrix_b, 16, 16, 16, __half, wmma::col_major> bf[4];
#pragma unroll
            for (int i = 0; i < 2; i++)
                wmma::load_matrix_sync(af[i], &As[(wm * 32 + i * 16) * LDA + ks], LDA);
#pragma unroll
            for (int j = 0; j < 4; j++)
                wmma::load_matrix_sync(bf[j], &Bs[(wn * 64 + j * 16) * LDA + ks], LDA);
#pragma unroll
            for (int i = 0; i < 2; i++)
#pragma unroll
                for (int j = 0; j < 4; j++)
                    wmma::mma_sync(cf[i][j], af[i], bf[j], cf[i][j]);
        }
        __syncthreads();
    }

#pragma unroll
    for (int i = 0; i < 2; i++)
#pragma unroll
        for (int j = 0; j < 4; j++)
            wmma::store_matrix_sync(&Cs[(wm * 32 + i * 16) * LDC + wn * 64 + j * 16],
                                    cf[i][j], LDC, wmma::mem_row_major);
    __syncthreads();

    {
        int r = t >> 1;
        int cb = (t & 1) * 64;
        int row = bm + r;
        if (row < M) {
#pragma unroll
            for (int j = 0; j < 64; j += 4) {
                float4 v = *(float4*)&Cs[r * LDC + cb + j];
                if (bias) {
                    float4 b = *(const float4*)(bias + cb + j);
                    v.x += b.x; v.y += b.y; v.z += b.z; v.w += b.w;
                }
                if (mode == 1) {
                    float4 rs = *(const float4*)(add + (size_t)row * HF + cb + j);
                    v.x = fmaxf(v.x, 0.f) + rs.x;
                    v.y = fmaxf(v.y, 0.f) + rs.y;
                    v.z = fmaxf(v.z, 0.f) + rs.z;
                    v.w = fmaxf(v.w, 0.f) + rs.w;
                }
                if (h_out) {
                    __half2 p[2] = {__floats2half2_rn(v.x, v.y),
                                    __floats2half2_rn(v.z, v.w)};
                    *(uint2*)(C0h + (size_t)row * HF + cb + j) = *(uint2*)p;
                } else {
                    float* Cf = (blockIdx.x == 0) ? C0f : C1f;
                    *(float4*)(Cf + (size_t)row * HF + cb + j) = v;
                }
            }
        }
    }
}

// ---------------- pull aggregation: warp per dst node ------------------------
__global__ void agg_kernel() {
    int warp = (blockIdx.x * blockDim.x + threadIdx.x) >> 5;
    if (warp >= NN) return;
    int lane = threadIdx.x & 31;

    int row = g_off[warp];
    int end = g_off[warp + 1];

    float z0 = 0.f, z1 = 0.f;
    for (int j = row + lane; j < end; j += 32) {
        float2 e = g_ep[j];
        z0 += e.x;
        z1 += e.y;
    }
#pragma unroll
    for (int off = 16; off > 0; off >>= 1) {
        z0 += __shfl_xor_sync(0xffffffff, z0, off);
        z1 += __shfl_xor_sync(0xffffffff, z1, off);
    }
    float invz = __fdividef(1.f, (lane < 16) ? z0 : z1);

    const int elem = lane * 4;
    float a0 = 0.f, a1 = 0.f, a2 = 0.f, a3 = 0.f;

    int j = row;
    for (; j + 2 <= end; j += 2) {
        float2 e0 = g_ep[j];
        float2 e1 = g_ep[j + 1];
        int s0 = g_psrc[j];
        int s1 = g_psrc[j + 1];
        float c0 = ((lane < 16) ? e0.x : e0.y) * invz;
        float c1 = ((lane < 16) ? e1.x : e1.y) * invz;
        const __half2* p0 = (const __half2*)(g_hsrc_h + (size_t)s0 * HF + elem);
        const __half2* p1 = (const __half2*)(g_hsrc_h + (size_t)s1 * HF + elem);
        __half2 u0 = p0[0], u1 = p0[1];
        __half2 v0 = p1[0], v1 = p1[1];
        float2 fu0 = __half22float2(u0), fu1 = __half22float2(u1);
        float2 fv0 = __half22float2(v0), fv1 = __half22float2(v1);
        a0 = fmaf(fu0.x, c0, a0); a1 = fmaf(fu0.y, c0, a1);
        a2 = fmaf(fu1.x, c0, a2); a3 = fmaf(fu1.y, c0, a3);
        a0 = fmaf(fv0.x, c1, a0); a1 = fmaf(fv0.y, c1, a1);
        a2 = fmaf(fv1.x, c1, a2); a3 = fmaf(fv1.y, c1, a3);
    }
    if (j < end) {
        float2 e0 = g_ep[j];
        int s0 = g_psrc[j];
        float c0 = ((lane < 16) ? e0.x : e0.y) * invz;
        const __half2* p0 = (const __half2*)(g_hsrc_h + (size_t)s0 * HF + elem);
        __half2 u0 = p0[0], u1 = p0[1];
        float2 fu0 = __half22float2(u0), fu1 = __half22float2(u1);
        a0 = fmaf(fu0.x, c0, a0); a1 = fmaf(fu0.y, c0, a1);
        a2 = fmaf(fu1.x, c0, a2); a3 = fmaf(fu1.y, c0, a3);
    }
    __half2 hh[2] = {__floats2half2_rn(a0, a1), __floats2half2_rn(a2, a3)};
    *(uint2*)(g_rst_h + (size_t)warp * HF + elem) = *(uint2*)hh;
}

// ---------------- launch -----------------------------------------------------
extern "C" void kernel_launch(void* const* d_in, const int* in_sizes, int n_in,
                              void* d_out, int out_size) {
    const float* feat_src    = (const float*)d_in[0];
    const float* feat_edge   = (const float*)d_in[1];
    const int*   edge_src    = (const int*)d_in[2];
    const int*   edge_dst    = (const int*)d_in[3];
    const float* W_src       = (const float*)d_in[4];
    const float* W_dst       = (const float*)d_in[5];
    const float* b_dst       = (const float*)d_in[6];
    const float* W_attn_src  = (const float*)d_in[7];
    const float* W_attn_dst  = (const float*)d_in[8];
    const float* W_attn_edge = (const float*)d_in[9];
    const float* W_ngnn      = (const float*)d_in[10];
    const float* b_ngnn      = (const float*)d_in[11];
    float* out = (float*)d_out;

    __half* feat_h;  cudaGetSymbolAddress((void**)&feat_h,  g_feat_h);
    __half* wsrc_h;  cudaGetSymbolAddress((void**)&wsrc_h,  g_wsrc_h);
    __half* wdst_h;  cudaGetSymbolAddress((void**)&wdst_h,  g_wdst_h);
    __half* wngnn_h; cudaGetSymbolAddress((void**)&wngnn_h, g_wngnn_h);
    __half* hsrc_h;  cudaGetSymbolAddress((void**)&hsrc_h,  g_hsrc_h);
    float*  hdst;    cudaGetSymbolAddress((void**)&hdst,    g_hdst);
    __half* rst_h;   cudaGetSymbolAddress((void**)&rst_h,   g_rst_h);
    int*    cnt;     cudaGetSymbolAddress((void**)&cnt,     g_cnt);

    static bool attr_set = false;
    if (!attr_set) {
        cudaFuncSetAttribute(gemm_h_kernel,
                             cudaFuncAttributeMaxDynamicSharedMemorySize,
                             128 * LDC * 4);
        attr_set = true;
    }
    const int dynsm = 128 * LDC * 4;

    // fused feat conversion + attention logits
    feat_attn_kernel<<<1024, 256>>>(feat_src, W_attn_src, W_attn_dst);

    // weight conversions (single launch)
    {
        int tot = 2 * (HF * DD / 8) + HF * HF / 8;
        wconv_kernel<<<(tot + 255) / 256, 256>>>(W_src, W_dst, W_ngnn);
    }

    // CSR build
    cudaMemsetAsync(cnt, 0, NN * sizeof(int));
    hist_kernel<<<(EE + 255) / 256, 256>>>(edge_dst);
    scan_kernel<<<1, 1024>>>();

    // fused scatter + edge logits + exp
    scatter_edge_kernel<<<(EE + 255) / 256, 256>>>(edge_src, edge_dst,
                                                   feat_edge, W_attn_edge);

    // node GEMMs: h_src (fp16 out) & h_dst (fp32 + bias)
    gemm_h_kernel<<<dim3(2, (NN + 127) / 128), 256, dynsm>>>(
        feat_h, wsrc_h, wdst_h, nullptr, b_dst, nullptr,
        nullptr, hdst, hsrc_h, NN, DD, 0);

    // pull aggregation (softmax + weighted sum), warp per dst
    agg_kernel<<<(NN * 32 + 255) / 256, 256>>>();

    // NGNN GEMM + ReLU + bias + residual -> out
    gemm_h_kernel<<<dim3(1, (NN + 127) / 128), 256, dynsm>>>(
        rst_h, wngnn_h, wngnn_h, b_ngnn, b_ngnn, hdst,
        out, out, nullptr, NN, HF, 1);
}

// round 6
// speedup vs baseline: 2.1773x; 1.4730x over previous
#include <cuda_runtime.h>
#include <cuda_fp16.h>
#include <mma.h>
#include <math.h>
#include <stdint.h>

using namespace nvcuda;

#define NN 100000
#define EE 1600000
#define DD 256
#define DE 8
#define HF 128
#define NEG_SLOPE 0.2f
#define NB ((NN + 1023) / 1024)   // scan blocks = 98

// ---------------- scratch (device globals) ----------------------------------
__device__ __half  g_feat_h[(size_t)NN * DD];   // fp16 feat_src
__device__ __half  g_wsrc_h[HF * DD];
__device__ __half  g_wdst_h[HF * DD];
__device__ __half  g_wngnn_h[HF * HF];
__device__ __half  g_hsrc_h[(size_t)NN * HF];   // fp16 h_src (gather payload)
__device__ float   g_hdst[(size_t)NN * HF];
__device__ __half  g_rst_h[(size_t)NN * HF];    // fp16 aggregation result
__device__ float2  g_asrc[NN];
__device__ float2  g_adst[NN];
__device__ float2  g_ep  [EE];                  // exp(e) in CSR order
__device__ int     g_cnt [NN];
__device__ int     g_off [NN + 1];
__device__ int     g_cur [NN];
__device__ int     g_psrc[EE];                  // src node per CSR slot
__device__ int     g_tmp [NN];                  // block-local exclusive scan
__device__ int     g_bsum[128];                 // per-block sums

// ---------------- fused: feat fp32->fp16 + attention logits ------------------
static __device__ __forceinline__ float dot8(float4 x0, float4 x1,
                                             float4 w0, float4 w1) {
    float s = x0.x * w0.x;
    s = fmaf(x0.y, w0.y, s); s = fmaf(x0.z, w0.z, s); s = fmaf(x0.w, w0.w, s);
    s = fmaf(x1.x, w1.x, s); s = fmaf(x1.y, w1.y, s);
    s = fmaf(x1.z, w1.z, s); s = fmaf(x1.w, w1.w, s);
    return s;
}

__global__ void feat_attn_kernel(const float* __restrict__ feat,
                                 const float* __restrict__ Was,
                                 const float* __restrict__ Wad) {
    int lane = threadIdx.x & 31;
    int warp = (blockIdx.x * blockDim.x + threadIdx.x) >> 5;
    int nwarps = (gridDim.x * blockDim.x) >> 5;
    int cb = lane * 8;

    float4 ws0a = *(const float4*)(Was + cb);
    float4 ws0b = *(const float4*)(Was + cb + 4);
    float4 ws1a = *(const float4*)(Was + DD + cb);
    float4 ws1b = *(const float4*)(Was + DD + cb + 4);
    float4 wd0a = *(const float4*)(Wad + cb);
    float4 wd0b = *(const float4*)(Wad + cb + 4);
    float4 wd1a = *(const float4*)(Wad + DD + cb);
    float4 wd1b = *(const float4*)(Wad + DD + cb + 4);

    for (int n = warp; n < NN; n += nwarps) {
        const float* fp = feat + (size_t)n * DD + cb;
        float4 x0 = *(const float4*)fp;
        float4 x1 = *(const float4*)(fp + 4);

        __half2 h[4] = {__floats2half2_rn(x0.x, x0.y),
                        __floats2half2_rn(x0.z, x0.w),
                        __floats2half2_rn(x1.x, x1.y),
                        __floats2half2_rn(x1.z, x1.w)};
        *(uint4*)(g_feat_h + (size_t)n * DD + cb) = *(uint4*)h;

        float s0 = dot8(x0, x1, ws0a, ws0b);
        float s1 = dot8(x0, x1, ws1a, ws1b);
        float d0 = dot8(x0, x1, wd0a, wd0b);
        float d1 = dot8(x0, x1, wd1a, wd1b);
#pragma unroll
        for (int off = 16; off > 0; off >>= 1) {
            s0 += __shfl_xor_sync(0xffffffff, s0, off);
            s1 += __shfl_xor_sync(0xffffffff, s1, off);
            d0 += __shfl_xor_sync(0xffffffff, d0, off);
            d1 += __shfl_xor_sync(0xffffffff, d1, off);
        }
        if (lane == 0) {
            g_asrc[n] = make_float2(s0, s1);
            g_adst[n] = make_float2(d0, d1);
        }
    }
}

// ---------------- weight conversions (one launch) ----------------------------
__global__ void wconv_kernel(const float* __restrict__ Wsrc,
                             const float* __restrict__ Wdst,
                             const float* __restrict__ Wngnn) {
    int i = blockIdx.x * blockDim.x + threadIdx.x;
    const int n1 = HF * DD / 8, n2 = 2 * n1, n3 = n2 + HF * HF / 8;
    const float* src;
    __half* dst;
    int k;
    if (i < n1)      { src = Wsrc;  dst = g_wsrc_h;  k = i; }
    else if (i < n2) { src = Wdst;  dst = g_wdst_h;  k = i - n1; }
    else if (i < n3) { src = Wngnn; dst = g_wngnn_h; k = i - n2; }
    else return;
    const float4* s = (const float4*)(src + (size_t)k * 8);
    float4 a = s[0], b = s[1];
    __half2 h[4] = {__floats2half2_rn(a.x, a.y), __floats2half2_rn(a.z, a.w),
                    __floats2half2_rn(b.x, b.y), __floats2half2_rn(b.z, b.w)};
    *(uint4*)(dst + (size_t)k * 8) = *(uint4*)h;
}

// ---------------- CSR build --------------------------------------------------
__global__ void hist_kernel(const int* __restrict__ ed) {
    int i = blockIdx.x * blockDim.x + threadIdx.x;
    if (i < EE) atomicAdd(&g_cnt[ed[i]], 1);
}

// phase 1: block-local exclusive scan + block sums
__global__ void scan1_kernel() {
    __shared__ int sh[1024];
    int t = threadIdx.x;
    int gi = blockIdx.x * 1024 + t;
    int v = (gi < NN) ? g_cnt[gi] : 0;
    sh[t] = v;
    __syncthreads();
#pragma unroll
    for (int off = 1; off < 1024; off <<= 1) {
        int add = (t >= off) ? sh[t - off] : 0;
        __syncthreads();
        sh[t] += add;
        __syncthreads();
    }
    if (gi < NN) g_tmp[gi] = sh[t] - v;      // exclusive within block
    if (t == 1023) g_bsum[blockIdx.x] = sh[1023];
}

// phase 2: exclusive scan of block sums (NB <= 128)
__global__ void scan2_kernel() {
    __shared__ int sh[128];
    int t = threadIdx.x;
    int v = (t < NB) ? g_bsum[t] : 0;
    sh[t] = v;
    __syncthreads();
#pragma unroll
    for (int off = 1; off < 128; off <<= 1) {
        int add = (t >= off) ? sh[t - off] : 0;
        __syncthreads();
        sh[t] += add;
        __syncthreads();
    }
    if (t < NB) g_bsum[t] = sh[t] - v;       // exclusive
}

// phase 3: combine, write g_off / g_cur
__global__ void scan3_kernel() {
    int i = blockIdx.x * blockDim.x + threadIdx.x;
    if (i < NN) {
        int o = g_tmp[i] + g_bsum[i >> 10];
        g_off[i] = o;
        g_cur[i] = o;
    }
    if (i == 0) g_off[NN] = EE;
}

// ---------------- fused: CSR scatter + edge logit + leaky + exp --------------
__global__ void scatter_edge_kernel(const int* __restrict__ es,
                                    const int* __restrict__ ed,
                                    const float* __restrict__ fe,
                                    const float* __restrict__ Wae) {
    int i = blockIdx.x * blockDim.x + threadIdx.x;
    if (i >= EE) return;

    int s = es[i], d = ed[i];
    int pos = atomicAdd(&g_cur[d], 1);
    g_psrc[pos] = s;

    float4 x0 = *(const float4*)(fe + (size_t)i * DE);
    float4 x1 = *(const float4*)(fe + (size_t)i * DE + 4);

    float ae0 = x0.x * __ldg(Wae + 0) + x0.y * __ldg(Wae + 1) +
                x0.z * __ldg(Wae + 2) + x0.w * __ldg(Wae + 3) +
                x1.x * __ldg(Wae + 4) + x1.y * __ldg(Wae + 5) +
                x1.z * __ldg(Wae + 6) + x1.w * __ldg(Wae + 7);
    float ae1 = x0.x * __ldg(Wae + 8)  + x0.y * __ldg(Wae + 9) +
                x0.z * __ldg(Wae + 10) + x0.w * __ldg(Wae + 11) +
                x1.x * __ldg(Wae + 12) + x1.y * __ldg(Wae + 13) +
                x1.z * __ldg(Wae + 14) + x1.w * __ldg(Wae + 15);

    float2 as = g_asrc[s];
    float2 ad = g_adst[d];
    float e0 = as.x + ad.x + ae0;
    float e1 = as.y + ad.y + ae1;
    e0 = (e0 >= 0.f) ? e0 : NEG_SLOPE * e0;
    e1 = (e1 >= 0.f) ? e1 : NEG_SLOPE * e1;
    g_ep[pos] = make_float2(__expf(e0), __expf(e1));
}

// ---------------- tensor-core GEMM: C[*,128] = A[M,K] @ B[128,K]^T ----------
#define LDA 40
#define LDC 132
__global__ void __launch_bounds__(256)
gemm_h_kernel(const __half* __restrict__ A,
              const __half* __restrict__ B0, const __half* __restrict__ B1,
              const float* __restrict__ bias0, const float* __restrict__ bias1,
              const float* __restrict__ add,
              float* __restrict__ C0f, float* __restrict__ C1f,
              __half* __restrict__ C0h,
              int M, int K, int mode) {
    extern __shared__ char dynsm[];
    __half* As = (__half*)dynsm;                       // [128][40]
    __half* Bs = (__half*)(dynsm + 128 * LDA * 2);     // [128][40]
    float*  Cs = (float*)dynsm;                        // [128][132] (reused)

    const __half* B    = (blockIdx.x == 0) ? B0 : B1;
    const float*  bias = (blockIdx.x == 0) ? bias0 : bias1;
    bool h_out = (blockIdx.x == 0) && (C0h != nullptr);

    int bm = blockIdx.y * 128;
    int t  = threadIdx.x;
    int w  = t >> 5;
    int wm = w & 3;
    int wn = w >> 2;

    wmma::fragment<wmma::accumulator, 16, 16, 16, float> cf[2][4];
#pragma unroll
    for (int i = 0; i < 2; i++)
#pragma unroll
        for (int j = 0; j < 4; j++) wmma::fill_fragment(cf[i][j], 0.0f);

    int lr = t >> 1;
    int lh = (t & 1) * 16;

    for (int kt = 0; kt < K; kt += 32) {
        {
            int arow = bm + lr;
            uint4 v0 = make_uint4(0, 0, 0, 0), v1 = v0;
            if (arow < M) {
                const __half* ap = A + (size_t)arow * K + kt + lh;
                v0 = *(const uint4*)ap;
                v1 = *(const uint4*)(ap + 8);
            }
            *(uint4*)&As[lr * LDA + lh] = v0;
            *(uint4*)&As[lr * LDA + lh + 8] = v1;
        }
        {
            const __half* bp = B + (size_t)lr * K + kt + lh;
            *(uint4*)&Bs[lr * LDA + lh] = *(const uint4*)bp;
            *(uint4*)&Bs[lr * LDA + lh + 8] = *(const uint4*)(bp + 8);
        }
        __syncthreads();

#pragma unroll
        for (int ks = 0; ks < 32; ks += 16) {
            wmma::fragment<wmma::matrix_a, 16, 16, 16, __half, wmma::row_major> af[2];
            wmma::fragment<wmma::matrix_b, 16, 16, 16, __half, wmma::col_major> bf[4];
#pragma unroll
            for (int i = 0; i < 2; i++)
                wmma::load_matrix_sync(af[i], &As[(wm * 32 + i * 16) * LDA + ks], LDA);
#pragma unroll
            for (int j = 0; j < 4; j++)
                wmma::load_matrix_sync(bf[j], &Bs[(wn * 64 + j * 16) * LDA + ks], LDA);
#pragma unroll
            for (int i = 0; i < 2; i++)
#pragma unroll
                for (int j = 0; j < 4; j++)
                    wmma::mma_sync(cf[i][j], af[i], bf[j], cf[i][j]);
        }
        __syncthreads();
    }

#pragma unroll
    for (int i = 0; i < 2; i++)
#pragma unroll
        for (int j = 0; j < 4; j++)
            wmma::store_matrix_sync(&Cs[(wm * 32 + i * 16) * LDC + wn * 64 + j * 16],
                                    cf[i][j], LDC, wmma::mem_row_major);
    __syncthreads();

    {
        int r = t >> 1;
        int cb = (t & 1) * 64;
        int row = bm + r;
        if (row < M) {
#pragma unroll
            for (int j = 0; j < 64; j += 4) {
                float4 v = *(float4*)&Cs[r * LDC + cb + j];
                if (bias) {
                    float4 b = *(const float4*)(bias + cb + j);
                    v.x += b.x; v.y += b.y; v.z += b.z; v.w += b.w;
                }
                if (mode == 1) {
                    float4 rs = *(const float4*)(add + (size_t)row * HF + cb + j);
                    v.x = fmaxf(v.x, 0.f) + rs.x;
                    v.y = fmaxf(v.y, 0.f) + rs.y;
                    v.z = fmaxf(v.z, 0.f) + rs.z;
                    v.w = fmaxf(v.w, 0.f) + rs.w;
                }
                if (h_out) {
                    __half2 p[2] = {__floats2half2_rn(v.x, v.y),
                                    __floats2half2_rn(v.z, v.w)};
                    *(uint2*)(C0h + (size_t)row * HF + cb + j) = *(uint2*)p;
                } else {
                    float* Cf = (blockIdx.x == 0) ? C0f : C1f;
                    *(float4*)(Cf + (size_t)row * HF + cb + j) = v;
                }
            }
        }
    }
}

// ---------------- pull aggregation: warp per dst node ------------------------
__global__ void agg_kernel() {
    int warp = (blockIdx.x * blockDim.x + threadIdx.x) >> 5;
    if (warp >= NN) return;
    int lane = threadIdx.x & 31;

    int row = g_off[warp];
    int end = g_off[warp + 1];

    float z0 = 0.f, z1 = 0.f;
    for (int j = row + lane; j < end; j += 32) {
        float2 e = g_ep[j];
        z0 += e.x;
        z1 += e.y;
    }
#pragma unroll
    for (int off = 16; off > 0; off >>= 1) {
        z0 += __shfl_xor_sync(0xffffffff, z0, off);
        z1 += __shfl_xor_sync(0xffffffff, z1, off);
    }
    float invz = __fdividef(1.f, (lane < 16) ? z0 : z1);

    const int elem = lane * 4;
    float a0 = 0.f, a1 = 0.f, a2 = 0.f, a3 = 0.f;

    int j = row;
    for (; j + 2 <= end; j += 2) {
        float2 e0 = g_ep[j];
        float2 e1 = g_ep[j + 1];
        int s0 = g_psrc[j];
        int s1 = g_psrc[j + 1];
        float c0 = ((lane < 16) ? e0.x : e0.y) * invz;
        float c1 = ((lane < 16) ? e1.x : e1.y) * invz;
        const __half2* p0 = (const __half2*)(g_hsrc_h + (size_t)s0 * HF + elem);
        const __half2* p1 = (const __half2*)(g_hsrc_h + (size_t)s1 * HF + elem);
        __half2 u0 = p0[0], u1 = p0[1];
        __half2 v0 = p1[0], v1 = p1[1];
        float2 fu0 = __half22float2(u0), fu1 = __half22float2(u1);
        float2 fv0 = __half22float2(v0), fv1 = __half22float2(v1);
        a0 = fmaf(fu0.x, c0, a0); a1 = fmaf(fu0.y, c0, a1);
        a2 = fmaf(fu1.x, c0, a2); a3 = fmaf(fu1.y, c0, a3);
        a0 = fmaf(fv0.x, c1, a0); a1 = fmaf(fv0.y, c1, a1);
        a2 = fmaf(fv1.x, c1, a2); a3 = fmaf(fv1.y, c1, a3);
    }
    if (j < end) {
        float2 e0 = g_ep[j];
        int s0 = g_psrc[j];
        float c0 = ((lane < 16) ? e0.x : e0.y) * invz;
        const __half2* p0 = (const __half2*)(g_hsrc_h + (size_t)s0 * HF + elem);
        __half2 u0 = p0[0], u1 = p0[1];
        float2 fu0 = __half22float2(u0), fu1 = __half22float2(u1);
        a0 = fmaf(fu0.x, c0, a0); a1 = fmaf(fu0.y, c0, a1);
        a2 = fmaf(fu1.x, c0, a2); a3 = fmaf(fu1.y, c0, a3);
    }
    __half2 hh[2] = {__floats2half2_rn(a0, a1), __floats2half2_rn(a2, a3)};
    *(uint2*)(g_rst_h + (size_t)warp * HF + elem) = *(uint2*)hh;
}

// ---------------- launch -----------------------------------------------------
extern "C" void kernel_launch(void* const* d_in, const int* in_sizes, int n_in,
                              void* d_out, int out_size) {
    const float* feat_src    = (const float*)d_in[0];
    const float* feat_edge   = (const float*)d_in[1];
    const int*   edge_src    = (const int*)d_in[2];
    const int*   edge_dst    = (const int*)d_in[3];
    const float* W_src       = (const float*)d_in[4];
    const float* W_dst       = (const float*)d_in[5];
    const float* b_dst       = (const float*)d_in[6];
    const float* W_attn_src  = (const float*)d_in[7];
    const float* W_attn_dst  = (const float*)d_in[8];
    const float* W_attn_edge = (const float*)d_in[9];
    const float* W_ngnn      = (const float*)d_in[10];
    const float* b_ngnn      = (const float*)d_in[11];
    float* out = (float*)d_out;

    __half* feat_h;  cudaGetSymbolAddress((void**)&feat_h,  g_feat_h);
    __half* wsrc_h;  cudaGetSymbolAddress((void**)&wsrc_h,  g_wsrc_h);
    __half* wdst_h;  cudaGetSymbolAddress((void**)&wdst_h,  g_wdst_h);
    __half* wngnn_h; cudaGetSymbolAddress((void**)&wngnn_h, g_wngnn_h);
    __half* hsrc_h;  cudaGetSymbolAddress((void**)&hsrc_h,  g_hsrc_h);
    float*  hdst;    cudaGetSymbolAddress((void**)&hdst,    g_hdst);
    __half* rst_h;   cudaGetSymbolAddress((void**)&rst_h,   g_rst_h);
    int*    cnt;     cudaGetSymbolAddress((void**)&cnt,     g_cnt);

    static bool attr_set = false;
    if (!attr_set) {
        cudaFuncSetAttribute(gemm_h_kernel,
                             cudaFuncAttributeMaxDynamicSharedMemorySize,
                             128 * LDC * 4);
        attr_set = true;
    }
    const int dynsm = 128 * LDC * 4;

    // fused feat conversion + attention logits
    feat_attn_kernel<<<1024, 256>>>(feat_src, W_attn_src, W_attn_dst);

    // weight conversions (single launch)
    {
        int tot = 2 * (HF * DD / 8) + HF * HF / 8;
        wconv_kernel<<<(tot + 255) / 256, 256>>>(W_src, W_dst, W_ngnn);
    }

    // CSR build: histogram + 3-phase parallel scan
    cudaMemsetAsync(cnt, 0, NN * sizeof(int));
    hist_kernel<<<(EE + 255) / 256, 256>>>(edge_dst);
    scan1_kernel<<<NB, 1024>>>();
    scan2_kernel<<<1, 128>>>();
    scan3_kernel<<<(NN + 255) / 256, 256>>>();

    // fused scatter + edge logits + exp
    scatter_edge_kernel<<<(EE + 255) / 256, 256>>>(edge_src, edge_dst,
                                                   feat_edge, W_attn_edge);

    // node GEMMs: h_src (fp16 out) & h_dst (fp32 + bias)
    gemm_h_kernel<<<dim3(2, (NN + 127) / 128), 256, dynsm>>>(
        feat_h, wsrc_h, wdst_h, nullptr, b_dst, nullptr,
        nullptr, hdst, hsrc_h, NN, DD, 0);

    // pull aggregation (softmax + weighted sum), warp per dst
    agg_kernel<<<(NN * 32 + 255) / 256, 256>>>();

    // NGNN GEMM + ReLU + bias + residual -> out
    gemm_h_kernel<<<dim3(1, (NN + 127) / 128), 256, dynsm>>>(
        rst_h, wngnn_h, wngnn_h, b_ngnn, b_ngnn, hdst,
        out, out, nullptr, NN, HF, 1);
}